// round 16
// baseline (speedup 1.0000x reference)
#include <cuda_runtime.h>
#include <cuda_bf16.h>
#include <stdint.h>
#include <math.h>

// Problem constants
#define B_    4
#define SEQ_  2048
#define DIM_  1024
#define HD_   128
#define NH_   8
#define NC_   16          // chunks
#define CK_   128         // chunk size
#define SCALE_ 0.088388347648318447f   // 1/sqrt(128)

// ---------------- scratch (static device globals; no allocation) -----------
__device__ float g_Qh[(size_t)B_*NH_*SEQ_*HD_];   // per-head projected Q=K=V
__device__ float g_gate[(size_t)B_*SEQ_*DIM_];    // swish(q@Wg+bg)
__device__ float g_Z [(size_t)B_*SEQ_*DIM_];      // gate * groupnorm(x)
__device__ float g_gpow[NH_*(SEQ_+1)];            // gamma^d tables
__device__ float g_rD  [NH_*SEQ_];                // 1/sqrt(colsum(D))[t]
__device__ float g_coef[B_*NH_*SEQ_];             // rD[t]/max(|cs[t]|,1)
__device__ float g_L    [B_*NH_*NC_*HD_];         // per-chunk scan partials
__device__ float g_carry[B_*NH_*NC_*HD_];         // scan carry into each chunk
__device__ float g_M[(size_t)B_*NH_*NC_*HD_*HD_]; // per-chunk K'^T V
__device__ float g_S[(size_t)B_*NH_*NC_*HD_*HD_]; // state at chunk starts

// ---------------- tf32 helpers ----------------------------------------------
__device__ __forceinline__ uint32_t f2tf(float x) {
    uint32_t r;
    asm("cvt.rna.tf32.f32 %0, %1;" : "=r"(r) : "f"(x));
    return r;
}
__device__ __forceinline__ void mma_tf32(float* c, const uint32_t* a, const uint32_t* b) {
    asm volatile(
        "mma.sync.aligned.m16n8k8.row.col.f32.tf32.tf32.f32 "
        "{%0,%1,%2,%3}, {%4,%5,%6,%7}, {%8,%9}, {%0,%1,%2,%3};"
        : "+f"(c[0]), "+f"(c[1]), "+f"(c[2]), "+f"(c[3])
        : "r"(a[0]), "r"(a[1]), "r"(a[2]), "r"(a[3]), "r"(b[0]), "r"(b[1]));
}

// ---------------- decay tables (parallel closed-form) -----------------------
__global__ void k_decay() {
    int h = blockIdx.x;
    double gamma = 1.0 - exp2(-5.0 - (double)h);
    double lg = log(gamma);
    double om = 1.0 - gamma;
    for (int d = threadIdx.x; d <= SEQ_; d += blockDim.x)
        g_gpow[h*(SEQ_+1)+d] = (float)exp((double)d * lg);
    for (int t = threadIdx.x; t < SEQ_; t += blockDim.x) {
        double denom = 1.0 - exp((double)(SEQ_-t)*lg);
        g_rD[h*SEQ_+t] = (float)sqrt(om/denom);
    }
}

// ---------------- per-head projection via single-TF32 mma (R13 form) --------
__global__ __launch_bounds__(256)
void k_proj_tc(const float* __restrict__ q, const float* __restrict__ Wq) {
    const int bh = blockIdx.y;
    const int b = bh / NH_, h = bh % NH_;
    const int s0 = blockIdx.x * 128;
    const float* A = q  + ((size_t)b*SEQ_ + s0)*DIM_ + h*HD_;
    const float* W = Wq + (size_t)h*HD_*HD_;

    __shared__ uint32_t As[128][36];
    __shared__ uint32_t Bs[32][136];
    const int tid  = threadIdx.x;
    const int lane = tid & 31, wid = tid >> 5;
    const int wm = (wid & 1) * 64, wn = (wid >> 1) * 32;
    const int gid = lane >> 2, tig = lane & 3;

    float c[4][4][4];
    #pragma unroll
    for (int mt=0;mt<4;mt++) for (int nt=0;nt<4;nt++) for (int r=0;r<4;r++) c[mt][nt][r]=0.f;

    for (int k0 = 0; k0 < HD_; k0 += 32) {
        #pragma unroll
        for (int i = 0; i < 4; i++) {
            int idx = tid + i*256;
            int row = idx >> 3, cg = (idx & 7) << 2;
            float4 v = *(const float4*)(A + (size_t)row*DIM_ + k0 + cg);
            As[row][cg+0]=f2tf(v.x); As[row][cg+1]=f2tf(v.y);
            As[row][cg+2]=f2tf(v.z); As[row][cg+3]=f2tf(v.w);
        }
        #pragma unroll
        for (int i = 0; i < 4; i++) {
            int idx = tid + i*256;
            int kr = idx >> 5, cg = (idx & 31) << 2;
            float4 v = *(const float4*)(W + (size_t)(k0+kr)*HD_ + cg);
            Bs[kr][cg+0]=f2tf(v.x); Bs[kr][cg+1]=f2tf(v.y);
            Bs[kr][cg+2]=f2tf(v.z); Bs[kr][cg+3]=f2tf(v.w);
        }
        __syncthreads();
        #pragma unroll
        for (int k8 = 0; k8 < 4; k8++) {
            const int ko = k8 * 8;
            uint32_t a[4][4], b[4][2];
            #pragma unroll
            for (int mt=0;mt<4;mt++) {
                int mr = wm + mt*16 + gid;
                a[mt][0] = As[mr    ][ko+tig  ];
                a[mt][1] = As[mr + 8][ko+tig  ];
                a[mt][2] = As[mr    ][ko+tig+4];
                a[mt][3] = As[mr + 8][ko+tig+4];
            }
            #pragma unroll
            for (int nt=0;nt<4;nt++) {
                int nc = wn + nt*8 + gid;
                b[nt][0] = Bs[ko+tig  ][nc];
                b[nt][1] = Bs[ko+tig+4][nc];
            }
            #pragma unroll
            for (int mt=0;mt<4;mt++)
                #pragma unroll
                for (int nt=0;nt<4;nt++)
                    mma_tf32(c[mt][nt], a[mt], b[nt]);
        }
        __syncthreads();
    }

    float* outp = g_Qh + ((size_t)bh*SEQ_ + s0)*HD_;
    #pragma unroll
    for (int nt=0;nt<4;nt++) {
        int col = wn + nt*8 + tig*2;
        #pragma unroll
        for (int mt=0;mt<4;mt++) {
            int row = wm + mt*16 + gid;
            *(float2*)(outp + (size_t)row*HD_ + col)     = make_float2(c[mt][nt][0], c[mt][nt][1]);
            *(float2*)(outp + (size_t)(row+8)*HD_ + col) = make_float2(c[mt][nt][2], c[mt][nt][3]);
        }
    }
}

// ---------------- TF32 tensor-core 1024-K GEMM (R13/R9 form) ----------------
template<int MODE>
__global__ __launch_bounds__(256)
void k_gemm_tc(const float* __restrict__ A, const float* __restrict__ Bm,
               const float* __restrict__ bias, float* __restrict__ C) {
    const int K = DIM_, N = DIM_;
    const int n0 = blockIdx.x * 128, m0 = blockIdx.y * 128;
    __shared__ uint32_t As[128][36];
    __shared__ uint32_t Bs[32][136];
    const int tid  = threadIdx.x;
    const int lane = tid & 31, wid = tid >> 5;
    const int wm = (wid & 1) * 64, wn = (wid >> 1) * 32;
    const int gid = lane >> 2, tig = lane & 3;

    float c[4][4][4];
    #pragma unroll
    for (int mt=0;mt<4;mt++)
        #pragma unroll
        for (int nt=0;nt<4;nt++)
            #pragma unroll
            for (int r=0;r<4;r++) c[mt][nt][r] = 0.f;

    for (int k0 = 0; k0 < K; k0 += 32) {
        #pragma unroll
        for (int i = 0; i < 4; i++) {
            int idx = tid + i*256;
            int row = idx >> 3, cg = (idx & 7) << 2;
            float4 v = *(const float4*)(A + (size_t)(m0+row)*K + k0 + cg);
            As[row][cg+0]=f2tf(v.x); As[row][cg+1]=f2tf(v.y);
            As[row][cg+2]=f2tf(v.z); As[row][cg+3]=f2tf(v.w);
        }
        #pragma unroll
        for (int i = 0; i < 4; i++) {
            int idx = tid + i*256;
            int kr = idx >> 5, cg = (idx & 31) << 2;
            float4 v = *(const float4*)(Bm + (size_t)(k0+kr)*N + n0 + cg);
            Bs[kr][cg+0]=f2tf(v.x); Bs[kr][cg+1]=f2tf(v.y);
            Bs[kr][cg+2]=f2tf(v.z); Bs[kr][cg+3]=f2tf(v.w);
        }
        __syncthreads();
        #pragma unroll
        for (int k8 = 0; k8 < 4; k8++) {
            const int ko = k8 * 8;
            uint32_t a[4][4], b[4][2];
            #pragma unroll
            for (int mt=0;mt<4;mt++) {
                int mr = wm + mt*16 + gid;
                a[mt][0] = As[mr    ][ko+tig  ];
                a[mt][1] = As[mr + 8][ko+tig  ];
                a[mt][2] = As[mr    ][ko+tig+4];
                a[mt][3] = As[mr + 8][ko+tig+4];
            }
            #pragma unroll
            for (int nt=0;nt<4;nt++) {
                int nc = wn + nt*8 + gid;
                b[nt][0] = Bs[ko+tig  ][nc];
                b[nt][1] = Bs[ko+tig+4][nc];
            }
            #pragma unroll
            for (int mt=0;mt<4;mt++)
                #pragma unroll
                for (int nt=0;nt<4;nt++)
                    mma_tf32(c[mt][nt], a[mt], b[nt]);
        }
        __syncthreads();
    }

    #pragma unroll
    for (int nt=0;nt<4;nt++) {
        int col = n0 + wn + nt*8 + tig*2;
        float bv0 = bias[col], bv1 = bias[col+1];
        #pragma unroll
        for (int mt=0;mt<4;mt++) {
            int row = m0 + wm + mt*16 + gid;
            #pragma unroll
            for (int half=0; half<2; half++) {
                int r = row + half*8;
                float v0 = c[mt][nt][half*2+0] + bv0;
                float v1 = c[mt][nt][half*2+1] + bv1;
                if (MODE == 0) {
                    v0 = v0 / (1.f + __expf(-v0));
                    v1 = v1 / (1.f + __expf(-v1));
                }
                *(float2*)(C + (size_t)r*N + col) = make_float2(v0, v1);
            }
        }
    }
}

// ---------------- blocked scan phase A: per-chunk weighted sums -------------
__global__ __launch_bounds__(128)
void k_chunkL() {
    int c = blockIdx.x, bh = blockIdx.y;
    int h = bh % NH_;
    int d = threadIdx.x;
    const float* Qc = g_Qh + ((size_t)bh*SEQ_ + c*CK_)*HD_;
    const float* gp = g_gpow + h*(SEQ_+1);
    float acc = 0.f;
    #pragma unroll 8
    for (int i = 0; i < CK_; i++)
        acc = fmaf(gp[i], Qc[(size_t)i*HD_ + d], acc);
    g_L[(bh*NC_ + c)*HD_ + d] = acc;
}

// ---------------- blocked scan phase B: cross-chunk carries -----------------
__global__ void k_carry() {
    int bh = blockIdx.x;
    int h = bh % NH_;
    int d = threadIdx.x;
    float g128 = g_gpow[h*(SEQ_+1) + CK_];
    float U = 0.f;
    for (int c = NC_-1; c >= 0; c--) {
        g_carry[(bh*NC_ + c)*HD_ + d] = U;
        U = fmaf(g128, U, g_L[(bh*NC_ + c)*HD_ + d]);
    }
}

// ---------------- blocked scan phase C: warp-per-chunk scan + coef ----------
__global__ __launch_bounds__(128)
void k_coef2() {
    int wid = threadIdx.x >> 5, lane = threadIdx.x & 31;
    int c = blockIdx.x * 4 + wid, bh = blockIdx.y;
    int h = bh % NH_;
    float gamma = 1.f - exp2f(-5.f - (float)h);
    const float* Qc  = g_Qh + ((size_t)bh*SEQ_ + c*CK_)*HD_;
    const float* rdp = g_rD + h*SEQ_ + c*CK_;
    float* cfp = g_coef + bh*SEQ_ + c*CK_;
    float4 u = *(const float4*)(g_carry + (bh*NC_ + c)*HD_ + lane*4);
    for (int r = CK_-1; r >= 0; r--) {
        float4 qv = *(const float4*)(Qc + (size_t)r*HD_ + lane*4);
        u.x = fmaf(gamma, u.x, qv.x);
        u.y = fmaf(gamma, u.y, qv.y);
        u.z = fmaf(gamma, u.z, qv.z);
        u.w = fmaf(gamma, u.w, qv.w);
        float p = qv.x*u.x + qv.y*u.y + qv.z*u.z + qv.w*u.w;
        #pragma unroll
        for (int o = 16; o; o >>= 1) p += __shfl_xor_sync(0xffffffffu, p, o);
        if (lane == 0) {
            float rd = rdp[r];
            float cs = rd * (p * SCALE_);
            cfp[r] = rd / fmaxf(fabsf(cs), 1.f);
        }
    }
}

// ---------------- per-chunk M_c = (w*Q)^T @ Q via single-TF32 mma ------------
#define CM_BYTES ((2*32*132)*4)
__global__ __launch_bounds__(256)
void k_chunkM() {
    extern __shared__ float smc[];
    float*    Qf = smc;                       // [32][132] fp32
    uint32_t* Bh = (uint32_t*)(smc + 32*132); // [32][132] tf32
    __shared__ float wk[32];

    const int c = blockIdx.x, bh = blockIdx.y;
    const int h = bh % NH_;
    const int t0 = c * CK_;
    const int tid = threadIdx.x;
    const int lane = tid & 31, wid = tid >> 5;
    const int gid = lane >> 2, tig = lane & 3;
    const int wm = (wid & 1) * 64, wn = (wid >> 1) * 32;

    const float* Qb = g_Qh + (size_t)bh*SEQ_*HD_;
    const float* gp = g_gpow + h*(SEQ_+1);
    const float* cf = g_coef + bh*SEQ_;

    float acc[4][4][4];
    #pragma unroll
    for (int mt=0;mt<4;mt++) for (int nt=0;nt<4;nt++) for (int r=0;r<4;r++) acc[mt][nt][r]=0.f;

    for (int k0 = 0; k0 < CK_; k0 += 32) {
        #pragma unroll
        for (int i = 0; i < 4; i++) {
            int idx = tid + i*256;
            int row = idx >> 5, c4 = (idx & 31) << 2;
            float4 v = *(const float4*)(Qb + (size_t)(t0+k0+row)*HD_ + c4);
            int base = row*132 + c4;
            Qf[base+0]=v.x; Qf[base+1]=v.y; Qf[base+2]=v.z; Qf[base+3]=v.w;
            Bh[base+0]=f2tf(v.x); Bh[base+1]=f2tf(v.y);
            Bh[base+2]=f2tf(v.z); Bh[base+3]=f2tf(v.w);
        }
        if (tid < 32)
            wk[tid] = gp[CK_ - (k0+tid)] * SCALE_ * cf[t0 + k0 + tid];
        __syncthreads();
        #pragma unroll
        for (int k8 = 0; k8 < 4; k8++) {
            const int ko = k8*8;
            float w0 = wk[ko+tig], w1 = wk[ko+tig+4];
            uint32_t a[4][4], b[4][2];
            #pragma unroll
            for (int mt=0;mt<4;mt++) {
                int mr = wm + mt*16 + gid;
                a[mt][0]=f2tf(w0 * Qf[(ko+tig  )*132 + mr    ]);
                a[mt][1]=f2tf(w0 * Qf[(ko+tig  )*132 + mr + 8]);
                a[mt][2]=f2tf(w1 * Qf[(ko+tig+4)*132 + mr    ]);
                a[mt][3]=f2tf(w1 * Qf[(ko+tig+4)*132 + mr + 8]);
            }
            #pragma unroll
            for (int nt=0;nt<4;nt++) {
                int nc = wn + nt*8 + gid;
                b[nt][0] = Bh[(ko+tig)*132 + nc];
                b[nt][1] = Bh[(ko+tig+4)*132 + nc];
            }
            #pragma unroll
            for (int mt=0;mt<4;mt++)
                #pragma unroll
                for (int nt=0;nt<4;nt++)
                    mma_tf32(acc[mt][nt], a[mt], b[nt]);
        }
        __syncthreads();
    }

    float* Mp = g_M + (size_t)(bh*NC_ + c)*HD_*HD_;
    #pragma unroll
    for (int nt=0;nt<4;nt++) {
        int col = wn + nt*8 + tig*2;
        #pragma unroll
        for (int mt=0;mt<4;mt++) {
            int row = wm + mt*16 + gid;
            *(float2*)(Mp + (size_t)row*HD_ + col)     = make_float2(acc[mt][nt][0], acc[mt][nt][1]);
            *(float2*)(Mp + (size_t)(row+8)*HD_ + col) = make_float2(acc[mt][nt][2], acc[mt][nt][3]);
        }
    }
}

// ---------------- state: S_c = sum_{j<c} g128^(c-1-j) * M_j (parallel) -------
__global__ __launch_bounds__(256)
void k_state() {
    int c = blockIdx.x, bh = blockIdx.y;
    int h = bh % NH_;
    float g128 = g_gpow[h*(SEQ_+1) + CK_];
    int tid = threadIdx.x;
    float4 acc[16];
    #pragma unroll
    for (int i=0;i<16;i++) acc[i] = make_float4(0.f,0.f,0.f,0.f);
    for (int j = 0; j < c; j++) {
        const float4* m = (const float4*)(g_M + (size_t)(bh*NC_ + j)*HD_*HD_);
        #pragma unroll
        for (int i=0;i<16;i++) {
            float4 mv = m[tid + i*256];
            acc[i].x = fmaf(g128, acc[i].x, mv.x);
            acc[i].y = fmaf(g128, acc[i].y, mv.y);
            acc[i].z = fmaf(g128, acc[i].z, mv.z);
            acc[i].w = fmaf(g128, acc[i].w, mv.w);
        }
    }
    float4* dst = (float4*)(g_S + (size_t)(bh*NC_ + c)*HD_*HD_);
    #pragma unroll
    for (int i=0;i<16;i++) dst[tid + i*256] = acc[i];
}

// ---------------- chunkwise output pass + fused GroupNorm/gate --------------
// GroupNorm reduction done in registers per warp-group; normalized values are
// staged through smem (Ps, free after stage d) so the gate read and Z write
// happen with fully coalesced float4 streams.
#define SM2_BYTES ((2*128*132)*4)
__global__ __launch_bounds__(256, 1)
void k_pass2ck(const float* __restrict__ beta) {
    extern __shared__ float smf[];
    uint32_t* Qhi = (uint32_t*)smf;           // [128][132] tf32 Q
    float*    Ps  = smf + 128*132;            // [128][132] fp32 P; reused: S tiles, then Z staging
    uint32_t* Shi = (uint32_t*)Ps;            // stage d: [32][132]

    const int tid = threadIdx.x;
    const int lane = tid & 31, wid = tid >> 5;
    const int gid = lane >> 2, tig = lane & 3;
    const int wm = (wid & 1) * 64, wn = (wid >> 1) * 32;
    const int c = blockIdx.x, bh = blockIdx.y;
    const int s0 = c * CK_;
    const int b = bh / NH_, h = bh % NH_;
    const float* Qb = g_Qh + ((size_t)bh*SEQ_ + s0)*HD_;
    const float* gp = g_gpow + h*(SEQ_+1);
    const float* cf = g_coef + bh*SEQ_ + s0;
    const float* Sc = g_S + (size_t)(bh*NC_ + c)*HD_*HD_;

    #pragma unroll
    for (int i = 0; i < 16; i++) {
        int idx = tid + i*256;
        int row = idx >> 5, c4 = (idx & 31) << 2;
        float4 v = *(const float4*)(Qb + (size_t)row*HD_ + c4);
        int base = row*132 + c4;
        Qhi[base+0]=f2tf(v.x); Qhi[base+1]=f2tf(v.y);
        Qhi[base+2]=f2tf(v.z); Qhi[base+3]=f2tf(v.w);
    }
    __syncthreads();

    float rowg[8];
    #pragma unroll
    for (int mt=0;mt<4;mt++) {
        rowg[mt*2+0] = gp[wm + mt*16 + gid];
        rowg[mt*2+1] = gp[wm + mt*16 + gid + 8];
    }
    float colinv[8], cfv[8];
    #pragma unroll
    for (int nt=0;nt<4;nt++) {
        int col0 = wn + nt*8 + tig*2;
        colinv[nt*2+0] = 1.f / gp[col0];
        colinv[nt*2+1] = 1.f / gp[col0+1];
        cfv[nt*2+0] = cf[col0];
        cfv[nt*2+1] = cf[col0+1];
    }

    // ---- stage a: S = Q@Q^T ----
    float Sf[4][4][4];
    #pragma unroll
    for (int mt=0;mt<4;mt++) for (int nt=0;nt<4;nt++) for (int r=0;r<4;r++) Sf[mt][nt][r]=0.f;
    #pragma unroll 4
    for (int k8 = 0; k8 < 16; k8++) {
        const int ko = k8*8;
        uint32_t a[4][4], b[4][2];
        #pragma unroll
        for (int mt=0;mt<4;mt++) {
            int mr = wm + mt*16 + gid;
            a[mt][0]=Qhi[mr*132+ko+tig];
            a[mt][1]=Qhi[(mr+8)*132+ko+tig];
            a[mt][2]=Qhi[mr*132+ko+tig+4];
            a[mt][3]=Qhi[(mr+8)*132+ko+tig+4];
        }
        #pragma unroll
        for (int nt=0;nt<4;nt++) {
            int nc = wn + nt*8 + gid;
            b[nt][0]=Qhi[nc*132+ko+tig];
            b[nt][1]=Qhi[nc*132+ko+tig+4];
        }
        #pragma unroll
        for (int mt=0;mt<4;mt++)
            #pragma unroll
            for (int nt=0;nt<4;nt++)
                mma_tf32(Sf[mt][nt], a[mt], b[nt]);
    }

    // ---- stage b: apply mask/decay/coef, write P fp32 to smem ----
    #pragma unroll
    for (int mt=0;mt<4;mt++) {
        #pragma unroll
        for (int nt=0;nt<4;nt++) {
            #pragma unroll
            for (int r=0;r<4;r++) {
                int rw = wm + mt*16 + gid + (r>>1)*8;
                int cl = wn + nt*8 + tig*2 + (r&1);
                float w = (rw >= cl) ? (SCALE_ * rowg[mt*2+(r>>1)] * colinv[nt*2+(r&1)] * cfv[nt*2+(r&1)]) : 0.f;
                Ps[rw*132 + cl] = Sf[mt][nt][r] * w;
            }
        }
    }
    __syncthreads();

    // ---- stage c: O1 = P @ Q ----
    float O1[4][4][4];
    #pragma unroll
    for (int mt=0;mt<4;mt++) for (int nt=0;nt<4;nt++) for (int r=0;r<4;r++) O1[mt][nt][r]=0.f;
    #pragma unroll 4
    for (int k8 = 0; k8 < 16; k8++) {
        const int ko = k8*8;
        uint32_t a[4][4], b[4][2];
        #pragma unroll
        for (int mt=0;mt<4;mt++) {
            int mr = wm + mt*16 + gid;
            a[mt][0]=f2tf(Ps[mr*132+ko+tig]);
            a[mt][1]=f2tf(Ps[(mr+8)*132+ko+tig]);
            a[mt][2]=f2tf(Ps[mr*132+ko+tig+4]);
            a[mt][3]=f2tf(Ps[(mr+8)*132+ko+tig+4]);
        }
        #pragma unroll
        for (int nt=0;nt<4;nt++) {
            int nc = wn + nt*8 + gid;
            b[nt][0]=Qhi[(ko+tig)*132+nc];
            b[nt][1]=Qhi[(ko+tig+4)*132+nc];
        }
        #pragma unroll
        for (int mt=0;mt<4;mt++)
            #pragma unroll
            for (int nt=0;nt<4;nt++)
                mma_tf32(O1[mt][nt], a[mt], b[nt]);
    }
    __syncthreads();

    // ---- stage d: O2 = Q @ S_c ----
    float O2[4][4][4];
    #pragma unroll
    for (int mt=0;mt<4;mt++) for (int nt=0;nt<4;nt++) for (int r=0;r<4;r++) O2[mt][nt][r]=0.f;
    for (int k0 = 0; k0 < HD_; k0 += 32) {
        #pragma unroll
        for (int i = 0; i < 4; i++) {
            int idx = tid + i*256;
            int row = idx >> 5, c4 = (idx & 31) << 2;
            float4 v = *(const float4*)(Sc + (size_t)(k0+row)*HD_ + c4);
            int base = row*132 + c4;
            Shi[base+0]=f2tf(v.x); Shi[base+1]=f2tf(v.y);
            Shi[base+2]=f2tf(v.z); Shi[base+3]=f2tf(v.w);
        }
        __syncthreads();
        #pragma unroll
        for (int k8 = 0; k8 < 4; k8++) {
            const int ko = k8*8;
            uint32_t a[4][4], b[4][2];
            #pragma unroll
            for (int mt=0;mt<4;mt++) {
                int mr = wm + mt*16 + gid;
                a[mt][0]=Qhi[mr*132+k0+ko+tig];
                a[mt][1]=Qhi[(mr+8)*132+k0+ko+tig];
                a[mt][2]=Qhi[mr*132+k0+ko+tig+4];
                a[mt][3]=Qhi[(mr+8)*132+k0+ko+tig+4];
            }
            #pragma unroll
            for (int nt=0;nt<4;nt++) {
                int nc = wn + nt*8 + gid;
                b[nt][0]=Shi[(ko+tig)*132+nc];
                b[nt][1]=Shi[(ko+tig+4)*132+nc];
            }
            #pragma unroll
            for (int mt=0;mt<4;mt++)
                #pragma unroll
                for (int nt=0;nt<4;nt++)
                    mma_tf32(O2[mt][nt], a[mt], b[nt]);
        }
        __syncthreads();
    }

    // ---- fused epilogue part 1: in-register GroupNorm (+beta) -> smem ------
    float bev[8];
    #pragma unroll
    for (int nt=0;nt<4;nt++) {
        int colg = h*HD_ + wn + nt*8 + tig*2;
        bev[nt*2+0] = beta[colg];
        bev[nt*2+1] = beta[colg+1];
    }
    #pragma unroll
    for (int mt=0;mt<4;mt++) {
        #pragma unroll
        for (int half=0; half<2; half++) {
            int row = wm + mt*16 + gid + half*8;
            float g = rowg[mt*2+half];
            float x[8];
            #pragma unroll
            for (int nt=0;nt<4;nt++) {
                x[nt*2+0] = O1[mt][nt][half*2+0] + g*O2[mt][nt][half*2+0];
                x[nt*2+1] = O1[mt][nt][half*2+1] + g*O2[mt][nt][half*2+1];
            }
            float s = 0.f;
            #pragma unroll
            for (int i=0;i<8;i++) s += x[i];
            s += __shfl_xor_sync(0xffffffffu, s, 1);
            s += __shfl_xor_sync(0xffffffffu, s, 2);
            float mu = s * (1.f/32.f);
            float sq = 0.f;
            #pragma unroll
            for (int i=0;i<8;i++) { float d = x[i]-mu; sq += d*d; }
            sq += __shfl_xor_sync(0xffffffffu, sq, 1);
            sq += __shfl_xor_sync(0xffffffffu, sq, 2);
            float inv = rsqrtf(sq * (1.f/32.f) + 1e-3f);
            #pragma unroll
            for (int nt=0;nt<4;nt++) {
                int col = wn + nt*8 + tig*2;
                Ps[row*132 + col    ] = (x[nt*2+0]-mu)*inv + bev[nt*2+0];
                Ps[row*132 + col + 1] = (x[nt*2+1]-mu)*inv + bev[nt*2+1];
            }
        }
    }
    __syncthreads();

    // ---- fused epilogue part 2: coalesced gate-read / Z-write sweep --------
    const float* Gp = g_gate + ((size_t)b*SEQ_ + s0)*DIM_ + h*HD_;
    float* Zp = g_Z + ((size_t)b*SEQ_ + s0)*DIM_ + h*HD_;
    #pragma unroll
    for (int i = 0; i < 16; i++) {
        int idx = tid + i*256;
        int row = idx >> 5, c4 = (idx & 31) << 2;
        float4 zn = *(float4*)&Ps[row*132 + c4];
        float4 gg = *(const float4*)(Gp + (size_t)row*DIM_ + c4);
        zn.x *= gg.x; zn.y *= gg.y; zn.z *= gg.z; zn.w *= gg.w;
        *(float4*)(Zp + (size_t)row*DIM_ + c4) = zn;
    }
}

// ---------------- launch ----------------------------------------------------
extern "C" void kernel_launch(void* const* d_in, const int* in_sizes, int n_in,
                              void* d_out, int out_size) {
    (void)in_sizes; (void)n_in; (void)out_size;
    const float* q    = (const float*)d_in[0];
    const float* Wqkv = (const float*)d_in[3];
    const float* Wg   = (const float*)d_in[4];
    const float* bg   = (const float*)d_in[5];
    const float* Wo   = (const float*)d_in[6];
    const float* bo   = (const float*)d_in[7];
    const float* beta = (const float*)d_in[8];
    float* out = (float*)d_out;

    float *p_gate = nullptr, *p_Z = nullptr;
    cudaGetSymbolAddress((void**)&p_gate, g_gate);
    cudaGetSymbolAddress((void**)&p_Z,    g_Z);
    cudaFuncSetAttribute(k_pass2ck, cudaFuncAttributeMaxDynamicSharedMemorySize, SM2_BYTES);
    cudaFuncSetAttribute(k_chunkM,  cudaFuncAttributeMaxDynamicSharedMemorySize, CM_BYTES);

    // k_gemm_tc<0> kept in the ncu-profiled slot (4th launch).
    k_decay<<<NH_, 256>>>();
    k_proj_tc<<<dim3(SEQ_/128, B_*NH_), 256>>>(q, Wqkv);
    k_chunkL<<<dim3(NC_, B_*NH_), HD_>>>();
    k_gemm_tc<0><<<dim3(DIM_/128, B_*SEQ_/128), 256>>>(q, Wg, bg, p_gate);
    k_carry<<<B_*NH_, HD_>>>();
    k_coef2<<<dim3(NC_/4, B_*NH_), 128>>>();
    k_chunkM<<<dim3(NC_, B_*NH_), 256, CM_BYTES>>>();
    k_state<<<dim3(NC_, B_*NH_), 256>>>();
    k_pass2ck<<<dim3(NC_, B_*NH_), 256, SM2_BYTES>>>(beta);
    k_gemm_tc<1><<<dim3(DIM_/128, B_*SEQ_/128), 256>>>(p_Z, Wo, bo, out);
}

// round 17
// speedup vs baseline: 1.2673x; 1.2673x over previous
#include <cuda_runtime.h>
#include <cuda_bf16.h>
#include <cuda_fp16.h>
#include <stdint.h>
#include <math.h>

// Problem constants
#define B_    4
#define SEQ_  2048
#define DIM_  1024
#define HD_   128
#define NH_   8
#define NC_   16          // chunks
#define CK_   128         // chunk size
#define SCALE_ 0.088388347648318447f   // 1/sqrt(128)

// ---------------- scratch (static device globals; no allocation) -----------
__device__ float g_Qh[(size_t)B_*NH_*SEQ_*HD_];   // per-head projected Q=K=V
__device__ float g_gate[(size_t)B_*SEQ_*DIM_];    // swish(q@Wg+bg)
__device__ float g_ho[(size_t)B_*NH_*SEQ_*HD_];   // retention head outputs
__device__ float g_Z [(size_t)B_*SEQ_*DIM_];      // gate * groupnorm(x)
__device__ float g_gpow[NH_*(SEQ_+1)];            // gamma^d tables
__device__ float g_rD  [NH_*SEQ_];                // 1/sqrt(colsum(D))[t]
__device__ float g_coef[B_*NH_*SEQ_];             // rD[t]/max(|cs[t]|,1)
__device__ float g_L    [B_*NH_*NC_*HD_];         // per-chunk scan partials
__device__ float g_carry[B_*NH_*NC_*HD_];         // scan carry into each chunk
__device__ float g_M[(size_t)B_*NH_*NC_*HD_*HD_]; // per-chunk K'^T V
__device__ float g_S[(size_t)B_*NH_*NC_*HD_*HD_]; // state at chunk starts

// ---------------- tf32 / fp16 helpers ----------------------------------------
__device__ __forceinline__ uint32_t f2tf(float x) {
    uint32_t r;
    asm("cvt.rna.tf32.f32 %0, %1;" : "=r"(r) : "f"(x));
    return r;
}
__device__ __forceinline__ void mma_tf32(float* c, const uint32_t* a, const uint32_t* b) {
    asm volatile(
        "mma.sync.aligned.m16n8k8.row.col.f32.tf32.tf32.f32 "
        "{%0,%1,%2,%3}, {%4,%5,%6,%7}, {%8,%9}, {%0,%1,%2,%3};"
        : "+f"(c[0]), "+f"(c[1]), "+f"(c[2]), "+f"(c[3])
        : "r"(a[0]), "r"(a[1]), "r"(a[2]), "r"(a[3]), "r"(b[0]), "r"(b[1]));
}
__device__ __forceinline__ uint32_t f22h(float a, float b) {
    __half2 h = __floats2half2_rn(a, b);
    return *(uint32_t*)&h;
}
__device__ __forceinline__ void mma_f16(float* c, const uint32_t* a, const uint32_t* b) {
    asm volatile(
        "mma.sync.aligned.m16n8k16.row.col.f32.f16.f16.f32 "
        "{%0,%1,%2,%3}, {%4,%5,%6,%7}, {%8,%9}, {%0,%1,%2,%3};"
        : "+f"(c[0]), "+f"(c[1]), "+f"(c[2]), "+f"(c[3])
        : "r"(a[0]), "r"(a[1]), "r"(a[2]), "r"(a[3]), "r"(b[0]), "r"(b[1]));
}

// ---------------- decay tables (parallel closed-form) -----------------------
__global__ void k_decay() {
    int h = blockIdx.x;
    double gamma = 1.0 - exp2(-5.0 - (double)h);
    double lg = log(gamma);
    double om = 1.0 - gamma;
    for (int d = threadIdx.x; d <= SEQ_; d += blockDim.x)
        g_gpow[h*(SEQ_+1)+d] = (float)exp((double)d * lg);
    for (int t = threadIdx.x; t < SEQ_; t += blockDim.x) {
        double denom = 1.0 - exp((double)(SEQ_-t)*lg);
        g_rD[h*SEQ_+t] = (float)sqrt(om/denom);
    }
}

// ---------------- per-head projection via single-TF32 mma (R13 form) --------
__global__ __launch_bounds__(256)
void k_proj_tc(const float* __restrict__ q, const float* __restrict__ Wq) {
    const int bh = blockIdx.y;
    const int b = bh / NH_, h = bh % NH_;
    const int s0 = blockIdx.x * 128;
    const float* A = q  + ((size_t)b*SEQ_ + s0)*DIM_ + h*HD_;
    const float* W = Wq + (size_t)h*HD_*HD_;

    __shared__ uint32_t As[128][36];
    __shared__ uint32_t Bs[32][136];
    const int tid  = threadIdx.x;
    const int lane = tid & 31, wid = tid >> 5;
    const int wm = (wid & 1) * 64, wn = (wid >> 1) * 32;
    const int gid = lane >> 2, tig = lane & 3;

    float c[4][4][4];
    #pragma unroll
    for (int mt=0;mt<4;mt++) for (int nt=0;nt<4;nt++) for (int r=0;r<4;r++) c[mt][nt][r]=0.f;

    for (int k0 = 0; k0 < HD_; k0 += 32) {
        #pragma unroll
        for (int i = 0; i < 4; i++) {
            int idx = tid + i*256;
            int row = idx >> 3, cg = (idx & 7) << 2;
            float4 v = *(const float4*)(A + (size_t)row*DIM_ + k0 + cg);
            As[row][cg+0]=f2tf(v.x); As[row][cg+1]=f2tf(v.y);
            As[row][cg+2]=f2tf(v.z); As[row][cg+3]=f2tf(v.w);
        }
        #pragma unroll
        for (int i = 0; i < 4; i++) {
            int idx = tid + i*256;
            int kr = idx >> 5, cg = (idx & 31) << 2;
            float4 v = *(const float4*)(W + (size_t)(k0+kr)*HD_ + cg);
            Bs[kr][cg+0]=f2tf(v.x); Bs[kr][cg+1]=f2tf(v.y);
            Bs[kr][cg+2]=f2tf(v.z); Bs[kr][cg+3]=f2tf(v.w);
        }
        __syncthreads();
        #pragma unroll
        for (int k8 = 0; k8 < 4; k8++) {
            const int ko = k8 * 8;
            uint32_t a[4][4], b[4][2];
            #pragma unroll
            for (int mt=0;mt<4;mt++) {
                int mr = wm + mt*16 + gid;
                a[mt][0] = As[mr    ][ko+tig  ];
                a[mt][1] = As[mr + 8][ko+tig  ];
                a[mt][2] = As[mr    ][ko+tig+4];
                a[mt][3] = As[mr + 8][ko+tig+4];
            }
            #pragma unroll
            for (int nt=0;nt<4;nt++) {
                int nc = wn + nt*8 + gid;
                b[nt][0] = Bs[ko+tig  ][nc];
                b[nt][1] = Bs[ko+tig+4][nc];
            }
            #pragma unroll
            for (int mt=0;mt<4;mt++)
                #pragma unroll
                for (int nt=0;nt<4;nt++)
                    mma_tf32(c[mt][nt], a[mt], b[nt]);
        }
        __syncthreads();
    }

    float* outp = g_Qh + ((size_t)bh*SEQ_ + s0)*HD_;
    #pragma unroll
    for (int nt=0;nt<4;nt++) {
        int col = wn + nt*8 + tig*2;
        #pragma unroll
        for (int mt=0;mt<4;mt++) {
            int row = wm + mt*16 + gid;
            *(float2*)(outp + (size_t)row*HD_ + col)     = make_float2(c[mt][nt][0], c[mt][nt][1]);
            *(float2*)(outp + (size_t)(row+8)*HD_ + col) = make_float2(c[mt][nt][2], c[mt][nt][3]);
        }
    }
}

// ---------------- FP16 tensor-core 1024-K GEMM: C = epi(A@B + bias) ---------
// m16n8k16 f16 mma (same 10-bit mantissa as tf32, 2x rate). A packed half2
// along k: As32[row][k2]; B packed half2 along k transposed: Bs32[k2][n].
template<int MODE>
__global__ __launch_bounds__(256)
void k_gemm_f16(const float* __restrict__ A, const float* __restrict__ Bm,
                const float* __restrict__ bias, float* __restrict__ C) {
    const int K = DIM_, N = DIM_;
    const int n0 = blockIdx.x * 128, m0 = blockIdx.y * 128;
    __shared__ uint32_t As32[128*20];   // [row][k2 0..15] pad 20
    __shared__ uint32_t Bs32[16*136];   // [k2 0..15][n 0..127] pad 136
    const int tid  = threadIdx.x;
    const int lane = tid & 31, wid = tid >> 5;
    const int wm = (wid & 1) * 64, wn = (wid >> 1) * 32;
    const int gid = lane >> 2, tig = lane & 3;

    float c[4][4][4];
    #pragma unroll
    for (int mt=0;mt<4;mt++)
        #pragma unroll
        for (int nt=0;nt<4;nt++)
            #pragma unroll
            for (int r=0;r<4;r++) c[mt][nt][r] = 0.f;

    for (int k0 = 0; k0 < K; k0 += 32) {
        // A tile: 128 rows x 32 k -> half2 pairs along k
        #pragma unroll
        for (int i = 0; i < 4; i++) {
            int idx = tid + i*256;
            int row = idx >> 3, cg = (idx & 7) << 2;     // k offsets cg..cg+3
            float4 v = *(const float4*)(A + (size_t)(m0+row)*K + k0 + cg);
            As32[row*20 + (cg>>1)    ] = f22h(v.x, v.y);
            As32[row*20 + (cg>>1) + 1] = f22h(v.z, v.w);
        }
        // B tile: 32 k x 128 n -> half2 pairs along k (reads 2 k-rows)
        #pragma unroll
        for (int i = 0; i < 2; i++) {
            int idx = tid + i*256;
            int k2 = idx >> 5, cg = (idx & 31) << 2;
            const float* b0p = Bm + (size_t)(k0 + 2*k2    )*N + n0 + cg;
            const float* b1p = Bm + (size_t)(k0 + 2*k2 + 1)*N + n0 + cg;
            float4 va = *(const float4*)b0p;
            float4 vb = *(const float4*)b1p;
            Bs32[k2*136 + cg+0] = f22h(va.x, vb.x);
            Bs32[k2*136 + cg+1] = f22h(va.y, vb.y);
            Bs32[k2*136 + cg+2] = f22h(va.z, vb.z);
            Bs32[k2*136 + cg+3] = f22h(va.w, vb.w);
        }
        __syncthreads();
        #pragma unroll
        for (int ks = 0; ks < 2; ks++) {            // two k16 steps
            uint32_t a[4][4], b[4][2];
            #pragma unroll
            for (int mt=0;mt<4;mt++) {
                int mr = wm + mt*16 + gid;
                a[mt][0] = As32[mr*20     + ks*8 + tig    ];
                a[mt][1] = As32[(mr+8)*20 + ks*8 + tig    ];
                a[mt][2] = As32[mr*20     + ks*8 + tig + 4];
                a[mt][3] = As32[(mr+8)*20 + ks*8 + tig + 4];
            }
            #pragma unroll
            for (int nt=0;nt<4;nt++) {
                int nc = wn + nt*8 + gid;
                b[nt][0] = Bs32[(ks*8 + tig    )*136 + nc];
                b[nt][1] = Bs32[(ks*8 + tig + 4)*136 + nc];
            }
            #pragma unroll
            for (int mt=0;mt<4;mt++)
                #pragma unroll
                for (int nt=0;nt<4;nt++)
                    mma_f16(c[mt][nt], a[mt], b[nt]);
        }
        __syncthreads();
    }

    #pragma unroll
    for (int nt=0;nt<4;nt++) {
        int col = n0 + wn + nt*8 + tig*2;
        float bv0 = bias[col], bv1 = bias[col+1];
        #pragma unroll
        for (int mt=0;mt<4;mt++) {
            int row = m0 + wm + mt*16 + gid;
            #pragma unroll
            for (int half=0; half<2; half++) {
                int r = row + half*8;
                float v0 = c[mt][nt][half*2+0] + bv0;
                float v1 = c[mt][nt][half*2+1] + bv1;
                if (MODE == 0) {
                    v0 = v0 / (1.f + __expf(-v0));
                    v1 = v1 / (1.f + __expf(-v1));
                }
                *(float2*)(C + (size_t)r*N + col) = make_float2(v0, v1);
            }
        }
    }
}

// ---------------- blocked scan phase A: per-chunk weighted sums -------------
__global__ __launch_bounds__(128)
void k_chunkL() {
    int c = blockIdx.x, bh = blockIdx.y;
    int h = bh % NH_;
    int d = threadIdx.x;
    const float* Qc = g_Qh + ((size_t)bh*SEQ_ + c*CK_)*HD_;
    const float* gp = g_gpow + h*(SEQ_+1);
    float acc = 0.f;
    #pragma unroll 8
    for (int i = 0; i < CK_; i++)
        acc = fmaf(gp[i], Qc[(size_t)i*HD_ + d], acc);
    g_L[(bh*NC_ + c)*HD_ + d] = acc;
}

// ---------------- blocked scan phase B: cross-chunk carries -----------------
__global__ void k_carry() {
    int bh = blockIdx.x;
    int h = bh % NH_;
    int d = threadIdx.x;
    float g128 = g_gpow[h*(SEQ_+1) + CK_];
    float U = 0.f;
    for (int c = NC_-1; c >= 0; c--) {
        g_carry[(bh*NC_ + c)*HD_ + d] = U;
        U = fmaf(g128, U, g_L[(bh*NC_ + c)*HD_ + d]);
    }
}

// ---------------- blocked scan phase C: warp-per-chunk scan + coef ----------
__global__ __launch_bounds__(128)
void k_coef2() {
    int wid = threadIdx.x >> 5, lane = threadIdx.x & 31;
    int c = blockIdx.x * 4 + wid, bh = blockIdx.y;
    int h = bh % NH_;
    float gamma = 1.f - exp2f(-5.f - (float)h);
    const float* Qc  = g_Qh + ((size_t)bh*SEQ_ + c*CK_)*HD_;
    const float* rdp = g_rD + h*SEQ_ + c*CK_;
    float* cfp = g_coef + bh*SEQ_ + c*CK_;
    float4 u = *(const float4*)(g_carry + (bh*NC_ + c)*HD_ + lane*4);
    for (int r = CK_-1; r >= 0; r--) {
        float4 qv = *(const float4*)(Qc + (size_t)r*HD_ + lane*4);
        u.x = fmaf(gamma, u.x, qv.x);
        u.y = fmaf(gamma, u.y, qv.y);
        u.z = fmaf(gamma, u.z, qv.z);
        u.w = fmaf(gamma, u.w, qv.w);
        float p = qv.x*u.x + qv.y*u.y + qv.z*u.z + qv.w*u.w;
        #pragma unroll
        for (int o = 16; o; o >>= 1) p += __shfl_xor_sync(0xffffffffu, p, o);
        if (lane == 0) {
            float rd = rdp[r];
            float cs = rd * (p * SCALE_);
            cfp[r] = rd / fmaxf(fabsf(cs), 1.f);
        }
    }
}

// ---------------- per-chunk M_c = (w*Q)^T @ Q via single-TF32 mma ------------
#define CM_BYTES ((2*32*132)*4)
__global__ __launch_bounds__(256)
void k_chunkM() {
    extern __shared__ float smc[];
    float*    Qf = smc;                       // [32][132] fp32
    uint32_t* Bh = (uint32_t*)(smc + 32*132); // [32][132] tf32
    __shared__ float wk[32];

    const int c = blockIdx.x, bh = blockIdx.y;
    const int h = bh % NH_;
    const int t0 = c * CK_;
    const int tid = threadIdx.x;
    const int lane = tid & 31, wid = tid >> 5;
    const int gid = lane >> 2, tig = lane & 3;
    const int wm = (wid & 1) * 64, wn = (wid >> 1) * 32;

    const float* Qb = g_Qh + (size_t)bh*SEQ_*HD_;
    const float* gp = g_gpow + h*(SEQ_+1);
    const float* cf = g_coef + bh*SEQ_;

    float acc[4][4][4];
    #pragma unroll
    for (int mt=0;mt<4;mt++) for (int nt=0;nt<4;nt++) for (int r=0;r<4;r++) acc[mt][nt][r]=0.f;

    for (int k0 = 0; k0 < CK_; k0 += 32) {
        #pragma unroll
        for (int i = 0; i < 4; i++) {
            int idx = tid + i*256;
            int row = idx >> 5, c4 = (idx & 31) << 2;
            float4 v = *(const float4*)(Qb + (size_t)(t0+k0+row)*HD_ + c4);
            int base = row*132 + c4;
            Qf[base+0]=v.x; Qf[base+1]=v.y; Qf[base+2]=v.z; Qf[base+3]=v.w;
            Bh[base+0]=f2tf(v.x); Bh[base+1]=f2tf(v.y);
            Bh[base+2]=f2tf(v.z); Bh[base+3]=f2tf(v.w);
        }
        if (tid < 32)
            wk[tid] = gp[CK_ - (k0+tid)] * SCALE_ * cf[t0 + k0 + tid];
        __syncthreads();
        #pragma unroll
        for (int k8 = 0; k8 < 4; k8++) {
            const int ko = k8*8;
            float w0 = wk[ko+tig], w1 = wk[ko+tig+4];
            uint32_t a[4][4], b[4][2];
            #pragma unroll
            for (int mt=0;mt<4;mt++) {
                int mr = wm + mt*16 + gid;
                a[mt][0]=f2tf(w0 * Qf[(ko+tig  )*132 + mr    ]);
                a[mt][1]=f2tf(w0 * Qf[(ko+tig  )*132 + mr + 8]);
                a[mt][2]=f2tf(w1 * Qf[(ko+tig+4)*132 + mr    ]);
                a[mt][3]=f2tf(w1 * Qf[(ko+tig+4)*132 + mr + 8]);
            }
            #pragma unroll
            for (int nt=0;nt<4;nt++) {
                int nc = wn + nt*8 + gid;
                b[nt][0] = Bh[(ko+tig)*132 + nc];
                b[nt][1] = Bh[(ko+tig+4)*132 + nc];
            }
            #pragma unroll
            for (int mt=0;mt<4;mt++)
                #pragma unroll
                for (int nt=0;nt<4;nt++)
                    mma_tf32(acc[mt][nt], a[mt], b[nt]);
        }
        __syncthreads();
    }

    float* Mp = g_M + (size_t)(bh*NC_ + c)*HD_*HD_;
    #pragma unroll
    for (int nt=0;nt<4;nt++) {
        int col = wn + nt*8 + tig*2;
        #pragma unroll
        for (int mt=0;mt<4;mt++) {
            int row = wm + mt*16 + gid;
            *(float2*)(Mp + (size_t)row*HD_ + col)     = make_float2(acc[mt][nt][0], acc[mt][nt][1]);
            *(float2*)(Mp + (size_t)(row+8)*HD_ + col) = make_float2(acc[mt][nt][2], acc[mt][nt][3]);
        }
    }
}

// ---------------- state: S_c = sum_{j<c} g128^(c-1-j) * M_j (parallel) -------
__global__ __launch_bounds__(256)
void k_state() {
    int c = blockIdx.x, bh = blockIdx.y;
    int h = bh % NH_;
    float g128 = g_gpow[h*(SEQ_+1) + CK_];
    int tid = threadIdx.x;
    float4 acc[16];
    #pragma unroll
    for (int i=0;i<16;i++) acc[i] = make_float4(0.f,0.f,0.f,0.f);
    for (int j = 0; j < c; j++) {
        const float4* m = (const float4*)(g_M + (size_t)(bh*NC_ + j)*HD_*HD_);
        #pragma unroll
        for (int i=0;i<16;i++) {
            float4 mv = m[tid + i*256];
            acc[i].x = fmaf(g128, acc[i].x, mv.x);
            acc[i].y = fmaf(g128, acc[i].y, mv.y);
            acc[i].z = fmaf(g128, acc[i].z, mv.z);
            acc[i].w = fmaf(g128, acc[i].w, mv.w);
        }
    }
    float4* dst = (float4*)(g_S + (size_t)(bh*NC_ + c)*HD_*HD_);
    #pragma unroll
    for (int i=0;i<16;i++) dst[tid + i*256] = acc[i];
}

// ---------------- chunkwise output pass (all stages single TF32) ------------
#define SM2_BYTES ((2*128*132)*4)
__global__ __launch_bounds__(256, 1)
void k_pass2ck() {
    extern __shared__ float smf[];
    uint32_t* Qhi = (uint32_t*)smf;           // [128][132] tf32 Q
    float*    Ps  = smf + 128*132;            // [128][132] fp32 P; reused in stage d
    uint32_t* Shi = (uint32_t*)Ps;            // stage d: [32][132]

    const int tid = threadIdx.x;
    const int lane = tid & 31, wid = tid >> 5;
    const int gid = lane >> 2, tig = lane & 3;
    const int wm = (wid & 1) * 64, wn = (wid >> 1) * 32;
    const int c = blockIdx.x, bh = blockIdx.y;
    const int s0 = c * CK_;
    const int h = bh % NH_;
    const float* Qb = g_Qh + ((size_t)bh*SEQ_ + s0)*HD_;
    const float* gp = g_gpow + h*(SEQ_+1);
    const float* cf = g_coef + bh*SEQ_ + s0;
    const float* Sc = g_S + (size_t)(bh*NC_ + c)*HD_*HD_;

    #pragma unroll
    for (int i = 0; i < 16; i++) {
        int idx = tid + i*256;
        int row = idx >> 5, c4 = (idx & 31) << 2;
        float4 v = *(const float4*)(Qb + (size_t)row*HD_ + c4);
        int base = row*132 + c4;
        Qhi[base+0]=f2tf(v.x); Qhi[base+1]=f2tf(v.y);
        Qhi[base+2]=f2tf(v.z); Qhi[base+3]=f2tf(v.w);
    }
    __syncthreads();

    float rowg[8];
    #pragma unroll
    for (int mt=0;mt<4;mt++) {
        rowg[mt*2+0] = gp[wm + mt*16 + gid];
        rowg[mt*2+1] = gp[wm + mt*16 + gid + 8];
    }
    float colinv[8], cfv[8];
    #pragma unroll
    for (int nt=0;nt<4;nt++) {
        int col0 = wn + nt*8 + tig*2;
        colinv[nt*2+0] = 1.f / gp[col0];
        colinv[nt*2+1] = 1.f / gp[col0+1];
        cfv[nt*2+0] = cf[col0];
        cfv[nt*2+1] = cf[col0+1];
    }

    // ---- stage a: S = Q@Q^T ----
    float Sf[4][4][4];
    #pragma unroll
    for (int mt=0;mt<4;mt++) for (int nt=0;nt<4;nt++) for (int r=0;r<4;r++) Sf[mt][nt][r]=0.f;
    #pragma unroll 4
    for (int k8 = 0; k8 < 16; k8++) {
        const int ko = k8*8;
        uint32_t a[4][4], b[4][2];
        #pragma unroll
        for (int mt=0;mt<4;mt++) {
            int mr = wm + mt*16 + gid;
            a[mt][0]=Qhi[mr*132+ko+tig];
            a[mt][1]=Qhi[(mr+8)*132+ko+tig];
            a[mt][2]=Qhi[mr*132+ko+tig+4];
            a[mt][3]=Qhi[(mr+8)*132+ko+tig+4];
        }
        #pragma unroll
        for (int nt=0;nt<4;nt++) {
            int nc = wn + nt*8 + gid;
            b[nt][0]=Qhi[nc*132+ko+tig];
            b[nt][1]=Qhi[nc*132+ko+tig+4];
        }
        #pragma unroll
        for (int mt=0;mt<4;mt++)
            #pragma unroll
            for (int nt=0;nt<4;nt++)
                mma_tf32(Sf[mt][nt], a[mt], b[nt]);
    }

    // ---- stage b: apply mask/decay/coef, write P fp32 to smem ----
    #pragma unroll
    for (int mt=0;mt<4;mt++) {
        #pragma unroll
        for (int nt=0;nt<4;nt++) {
            #pragma unroll
            for (int r=0;r<4;r++) {
                int rw = wm + mt*16 + gid + (r>>1)*8;
                int cl = wn + nt*8 + tig*2 + (r&1);
                float w = (rw >= cl) ? (SCALE_ * rowg[mt*2+(r>>1)] * colinv[nt*2+(r&1)] * cfv[nt*2+(r&1)]) : 0.f;
                Ps[rw*132 + cl] = Sf[mt][nt][r] * w;
            }
        }
    }
    __syncthreads();

    // ---- stage c: O1 = P @ Q ----
    float O1[4][4][4];
    #pragma unroll
    for (int mt=0;mt<4;mt++) for (int nt=0;nt<4;nt++) for (int r=0;r<4;r++) O1[mt][nt][r]=0.f;
    #pragma unroll 4
    for (int k8 = 0; k8 < 16; k8++) {
        const int ko = k8*8;
        uint32_t a[4][4], b[4][2];
        #pragma unroll
        for (int mt=0;mt<4;mt++) {
            int mr = wm + mt*16 + gid;
            a[mt][0]=f2tf(Ps[mr*132+ko+tig]);
            a[mt][1]=f2tf(Ps[(mr+8)*132+ko+tig]);
            a[mt][2]=f2tf(Ps[mr*132+ko+tig+4]);
            a[mt][3]=f2tf(Ps[(mr+8)*132+ko+tig+4]);
        }
        #pragma unroll
        for (int nt=0;nt<4;nt++) {
            int nc = wn + nt*8 + gid;
            b[nt][0]=Qhi[(ko+tig)*132+nc];
            b[nt][1]=Qhi[(ko+tig+4)*132+nc];
        }
        #pragma unroll
        for (int mt=0;mt<4;mt++)
            #pragma unroll
            for (int nt=0;nt<4;nt++)
                mma_tf32(O1[mt][nt], a[mt], b[nt]);
    }
    __syncthreads();

    // ---- stage d: O2 = Q @ S_c ----
    float O2[4][4][4];
    #pragma unroll
    for (int mt=0;mt<4;mt++) for (int nt=0;nt<4;nt++) for (int r=0;r<4;r++) O2[mt][nt][r]=0.f;
    for (int k0 = 0; k0 < HD_; k0 += 32) {
        #pragma unroll
        for (int i = 0; i < 4; i++) {
            int idx = tid + i*256;
            int row = idx >> 5, c4 = (idx & 31) << 2;
            float4 v = *(const float4*)(Sc + (size_t)(k0+row)*HD_ + c4);
            int base = row*132 + c4;
            Shi[base+0]=f2tf(v.x); Shi[base+1]=f2tf(v.y);
            Shi[base+2]=f2tf(v.z); Shi[base+3]=f2tf(v.w);
        }
        __syncthreads();
        #pragma unroll
        for (int k8 = 0; k8 < 4; k8++) {
            const int ko = k8*8;
            uint32_t a[4][4], b[4][2];
            #pragma unroll
            for (int mt=0;mt<4;mt++) {
                int mr = wm + mt*16 + gid;
                a[mt][0]=Qhi[mr*132+k0+ko+tig];
                a[mt][1]=Qhi[(mr+8)*132+k0+ko+tig];
                a[mt][2]=Qhi[mr*132+k0+ko+tig+4];
                a[mt][3]=Qhi[(mr+8)*132+k0+ko+tig+4];
            }
            #pragma unroll
            for (int nt=0;nt<4;nt++) {
                int nc = wn + nt*8 + gid;
                b[nt][0]=Shi[(ko+tig)*132+nc];
                b[nt][1]=Shi[(ko+tig+4)*132+nc];
            }
            #pragma unroll
            for (int mt=0;mt<4;mt++)
                #pragma unroll
                for (int nt=0;nt<4;nt++)
                    mma_tf32(O2[mt][nt], a[mt], b[nt]);
        }
        __syncthreads();
    }

    // ---- epilogue: out = O1 + gamma^row * O2 ----
    float* outp = g_ho + ((size_t)bh*SEQ_ + s0)*HD_;
    #pragma unroll
    for (int nt=0;nt<4;nt++) {
        int col = wn + nt*8 + tig*2;
        #pragma unroll
        for (int mt=0;mt<4;mt++) {
            int row = wm + mt*16 + gid;
            float g0 = rowg[mt*2+0], g1 = rowg[mt*2+1];
            float2 o0 = make_float2(O1[mt][nt][0] + g0*O2[mt][nt][0],
                                    O1[mt][nt][1] + g0*O2[mt][nt][1]);
            float2 o1 = make_float2(O1[mt][nt][2] + g1*O2[mt][nt][2],
                                    O1[mt][nt][3] + g1*O2[mt][nt][3]);
            *(float2*)(outp + (size_t)row*HD_ + col)     = o0;
            *(float2*)(outp + (size_t)(row+8)*HD_ + col) = o1;
        }
    }
}

// ---------------- GroupNorm(32 groups) + beta, then gate --------------------
__global__ __launch_bounds__(256)
void k_gn(const float* __restrict__ beta) {
    int row = blockIdx.x;
    int b = row >> 11, s = row & (SEQ_-1);
    int tid = threadIdx.x;
    int c = tid << 2;
    int h = c >> 7, d = c & 127;
    float4 x = *(const float4*)(g_ho + (((size_t)(b*NH_+h)*SEQ_ + s)*HD_ + d));

    float sum = x.x + x.y + x.z + x.w;
    #pragma unroll
    for (int o = 1; o < 8; o <<= 1) sum += __shfl_xor_sync(0xffffffffu, sum, o);
    float mu = sum * (1.f/32.f);

    float dx0 = x.x-mu, dx1 = x.y-mu, dx2 = x.z-mu, dx3 = x.w-mu;
    float sq = dx0*dx0 + dx1*dx1 + dx2*dx2 + dx3*dx3;
    #pragma unroll
    for (int o = 1; o < 8; o <<= 1) sq += __shfl_xor_sync(0xffffffffu, sq, o);
    float inv = rsqrtf(sq * (1.f/32.f) + 1e-3f);

    float4 be = *(const float4*)(beta + c);
    float4 g  = *(const float4*)(g_gate + (size_t)row*DIM_ + c);
    float4 z;
    z.x = (dx0*inv + be.x) * g.x;
    z.y = (dx1*inv + be.y) * g.y;
    z.z = (dx2*inv + be.z) * g.z;
    z.w = (dx3*inv + be.w) * g.w;
    *(float4*)(g_Z + (size_t)row*DIM_ + c) = z;
}

// ---------------- launch ----------------------------------------------------
extern "C" void kernel_launch(void* const* d_in, const int* in_sizes, int n_in,
                              void* d_out, int out_size) {
    (void)in_sizes; (void)n_in; (void)out_size;
    const float* q    = (const float*)d_in[0];
    const float* Wqkv = (const float*)d_in[3];
    const float* Wg   = (const float*)d_in[4];
    const float* bg   = (const float*)d_in[5];
    const float* Wo   = (const float*)d_in[6];
    const float* bo   = (const float*)d_in[7];
    const float* beta = (const float*)d_in[8];
    float* out = (float*)d_out;

    float *p_gate = nullptr, *p_Z = nullptr;
    cudaGetSymbolAddress((void**)&p_gate, g_gate);
    cudaGetSymbolAddress((void**)&p_Z,    g_Z);
    cudaFuncSetAttribute(k_pass2ck, cudaFuncAttributeMaxDynamicSharedMemorySize, SM2_BYTES);
    cudaFuncSetAttribute(k_chunkM,  cudaFuncAttributeMaxDynamicSharedMemorySize, CM_BYTES);

    // k_gemm_f16<0> kept in the ncu-profiled slot (4th launch).
    k_decay<<<NH_, 256>>>();
    k_proj_tc<<<dim3(SEQ_/128, B_*NH_), 256>>>(q, Wqkv);
    k_chunkL<<<dim3(NC_, B_*NH_), HD_>>>();
    k_gemm_f16<0><<<dim3(DIM_/128, B_*SEQ_/128), 256>>>(q, Wg, bg, p_gate);
    k_carry<<<B_*NH_, HD_>>>();
    k_coef2<<<dim3(NC_/4, B_*NH_), 128>>>();
    k_chunkM<<<dim3(NC_, B_*NH_), 256, CM_BYTES>>>();
    k_state<<<dim3(NC_, B_*NH_), 256>>>();
    k_pass2ck<<<dim3(NC_, B_*NH_), 256, SM2_BYTES>>>();
    k_gn<<<B_*SEQ_, 256>>>(beta);
    k_gemm_f16<1><<<dim3(DIM_/128, B_*SEQ_/128), 256>>>(p_Z, Wo, bo, out);
}